// round 9
// baseline (speedup 1.0000x reference)
#include <cuda_runtime.h>
#include <math.h>

#define N_ROWS 8192
#define N_COLS 512
#define GRID_A 512
#define THREADS_A 256
#define WARPS_A 8              /* 512 blocks * 8 warps * 2 rows = 8192 rows */
#define NREP 8                 /* column replicas  */
#define SREP 64                /* scalar replicas  */

#define SCALE_D   4294967296.0          /* 2^32 */
#define INV_SCALE (1.0 / 4294967296.0)

// Order-invariant integer accumulators (zero-init; finalize kernel resets).
__device__ unsigned long long g_col_ll[NREP][N_COLS];
__device__ unsigned long long g_S_ll[SREP];
__device__ int g_max_int[SREP];         // bit-cast float, values >= 0

__global__ void __launch_bounds__(THREADS_A)
stream_kernel(const float* __restrict__ x) {
    __shared__ float s_colw[WARPS_A][N_COLS];   // 16 KB

    const int tid = threadIdx.x;
    const int wid = tid >> 5;
    const int lid = tid & 31;

    // ---- warp owns 2 rows; 8 named float4 loads, all issued up front ----
    const int row0 = (blockIdx.x * WARPS_A + wid) * 2;
    const float4* p0 = reinterpret_cast<const float4*>(x + (size_t)row0 * N_COLS);
    const float4* p1 = p0 + 128;

    const float4 a0 = p0[lid];      const float4 a1 = p0[32 + lid];
    const float4 a2 = p0[64 + lid]; const float4 a3 = p0[96 + lid];
    const float4 b0 = p1[lid];      const float4 b1 = p1[32 + lid];
    const float4 b2 = p1[64 + lid]; const float4 b3 = p1[96 + lid];

    // column partials into smem (vectorized, conflict-free)
    float4 c0, c1, c2, c3;
    c0.x = a0.x + b0.x; c0.y = a0.y + b0.y; c0.z = a0.z + b0.z; c0.w = a0.w + b0.w;
    c1.x = a1.x + b1.x; c1.y = a1.y + b1.y; c1.z = a1.z + b1.z; c1.w = a1.w + b1.w;
    c2.x = a2.x + b2.x; c2.y = a2.y + b2.y; c2.z = a2.z + b2.z; c2.w = a2.w + b2.w;
    c3.x = a3.x + b3.x; c3.y = a3.y + b3.y; c3.z = a3.z + b3.z; c3.w = a3.w + b3.w;
    *reinterpret_cast<float4*>(&s_colw[wid][0   + lid * 4]) = c0;
    *reinterpret_cast<float4*>(&s_colw[wid][128 + lid * 4]) = c1;
    *reinterpret_cast<float4*>(&s_colw[wid][256 + lid * 4]) = c2;
    *reinterpret_cast<float4*>(&s_colw[wid][384 + lid * 4]) = c3;

    float sq0 = a0.x*a0.x + a0.y*a0.y + a0.z*a0.z + a0.w*a0.w
              + a1.x*a1.x + a1.y*a1.y + a1.z*a1.z + a1.w*a1.w
              + a2.x*a2.x + a2.y*a2.y + a2.z*a2.z + a2.w*a2.w
              + a3.x*a3.x + a3.y*a3.y + a3.z*a3.z + a3.w*a3.w;
    float sq1 = b0.x*b0.x + b0.y*b0.y + b0.z*b0.z + b0.w*b0.w
              + b1.x*b1.x + b1.y*b1.y + b1.z*b1.z + b1.w*b1.w
              + b2.x*b2.x + b2.y*b2.y + b2.z*b2.z + b2.w*b2.w
              + b3.x*b3.x + b3.y*b3.y + b3.z*b3.z + b3.w*b3.w;

    #pragma unroll
    for (int off = 16; off > 0; off >>= 1) {
        sq0 += __shfl_xor_sync(0xffffffffu, sq0, off);
        sq1 += __shfl_xor_sync(0xffffffffu, sq1, off);
    }
    // fire-and-forget (RED, no scoreboard wait): per-warp S and max
    if (lid == 0) {
        const int rs = (blockIdx.x * WARPS_A + wid) & (SREP - 1);
        atomicAdd(&g_S_ll[rs],
                  (unsigned long long)__double2ll_rn((double)(sq0 + sq1) * SCALE_D));
        atomicMax(&g_max_int[rs], __float_as_int(fmaxf(sq0, sq1)));
    }
    __syncthreads();

    // ---- combine 8 warps, push column REDs (no return -> REDG) ----
    const int rep = blockIdx.x & (NREP - 1);
    #pragma unroll
    for (int k = 0; k < 2; ++k) {
        const int c = tid + k * THREADS_A;
        float v = 0.f;
        #pragma unroll
        for (int w = 0; w < WARPS_A; ++w) v += s_colw[w][c];
        atomicAdd(&g_col_ll[rep][c],
                  (unsigned long long)__double2ll_rn((double)v * SCALE_D));
    }
}

__global__ void __launch_bounds__(512)
finalize_kernel(float* __restrict__ out) {
    __shared__ double s_w[16];
    __shared__ double s_sm[2];
    __shared__ float  s_mx[2];

    const int tid = threadIdx.x;
    const int wid = tid >> 5;
    const int lid = tid & 31;

    // column totals: one column per thread, NREP replicas each
    long long t = 0ll;
    #pragma unroll
    for (int r = 0; r < NREP; ++r)
        t += (long long)g_col_ll[r][tid];
    const double d = (double)t * INV_SCALE;
    double csq = d * d;

    #pragma unroll
    for (int off = 16; off > 0; off >>= 1)
        csq += __shfl_xor_sync(0xffffffffu, csq, off);
    if (lid == 0) s_w[wid] = csq;

    // S and max from replicated scalars (threads 0..63 = warps 0..1)
    if (tid < SREP) {
        double Sp = (double)(long long)g_S_ll[tid] * INV_SCALE;
        float  Mp = __int_as_float(g_max_int[tid]);
        #pragma unroll
        for (int off = 16; off > 0; off >>= 1) {
            Sp += __shfl_xor_sync(0xffffffffu, Sp, off);
            Mp = fmaxf(Mp, __shfl_xor_sync(0xffffffffu, Mp, off));
        }
        if (lid == 0) { s_sm[wid] = Sp; s_mx[wid] = Mp; }
    }
    __syncthreads();

    if (tid == 0) {
        double ssq_total = 0.0;
        #pragma unroll
        for (int w = 0; w < 16; ++w) ssq_total += s_w[w];
        const double S_total = s_sm[0] + s_sm[1];
        const double maxsq = (double)fmaxf(s_mx[0], s_mx[1]);
        const double numer = (double)N_ROWS * S_total - ssq_total;
        const double norm  = sqrt(maxsq);
        const double count = (double)N_ROWS * (double)(N_ROWS - 1) * 0.5;
        out[0] = (float)(numer / (norm * count));
    }
    __syncthreads();   // all reads done -> safe to reset

    #pragma unroll
    for (int r = 0; r < NREP; ++r)
        g_col_ll[r][tid] = 0ull;
    if (tid < SREP) {
        g_S_ll[tid] = 0ull;
        g_max_int[tid] = 0;
    }
}

extern "C" void kernel_launch(void* const* d_in, const int* in_sizes, int n_in,
                              void* d_out, int out_size) {
    (void)in_sizes; (void)n_in; (void)out_size;
    const float* x = (const float*)d_in[0];
    float* out = (float*)d_out;
    stream_kernel<<<GRID_A, THREADS_A>>>(x);
    finalize_kernel<<<1, 512>>>(out);
}

// round 10
// speedup vs baseline: 1.1373x; 1.1373x over previous
#include <cuda_runtime.h>
#include <math.h>

#define N_ROWS 8192
#define N_COLS 512
#define GRID_A 512
#define THREADS_A 256
#define WARPS_A 8              /* 512 blocks * 8 warps * 2 rows = 8192 rows */
#define NREP 16                /* column replicas  */
#define SREP 64                /* scalar replicas  */

#define SCALE_F   4294967296.0f         /* 2^32, exact in float */
#define INV_SCALE_F (1.0f / 4294967296.0f)

// Order-invariant integer accumulators (zero-init; finalize kernel resets).
__device__ unsigned long long g_col_ll[NREP][N_COLS];
__device__ unsigned long long g_S_ll[SREP];
__device__ int g_max_int[SREP];         // bit-cast float, values >= 0

__global__ void __launch_bounds__(THREADS_A)
stream_kernel(const float* __restrict__ x) {
    __shared__ float s_colw[WARPS_A][N_COLS];   // 16 KB

    const int tid = threadIdx.x;
    const int wid = tid >> 5;
    const int lid = tid & 31;

    // ---- warp owns 2 rows; 8 named float4 loads, all issued up front ----
    const int row0 = (blockIdx.x * WARPS_A + wid) * 2;
    const float4* p0 = reinterpret_cast<const float4*>(x + (size_t)row0 * N_COLS);
    const float4* p1 = p0 + 128;

    const float4 a0 = p0[lid];      const float4 a1 = p0[32 + lid];
    const float4 a2 = p0[64 + lid]; const float4 a3 = p0[96 + lid];
    const float4 b0 = p1[lid];      const float4 b1 = p1[32 + lid];
    const float4 b2 = p1[64 + lid]; const float4 b3 = p1[96 + lid];

    // column partials into smem (vectorized, conflict-free)
    float4 c0, c1, c2, c3;
    c0.x = a0.x + b0.x; c0.y = a0.y + b0.y; c0.z = a0.z + b0.z; c0.w = a0.w + b0.w;
    c1.x = a1.x + b1.x; c1.y = a1.y + b1.y; c1.z = a1.z + b1.z; c1.w = a1.w + b1.w;
    c2.x = a2.x + b2.x; c2.y = a2.y + b2.y; c2.z = a2.z + b2.z; c2.w = a2.w + b2.w;
    c3.x = a3.x + b3.x; c3.y = a3.y + b3.y; c3.z = a3.z + b3.z; c3.w = a3.w + b3.w;
    *reinterpret_cast<float4*>(&s_colw[wid][0   + lid * 4]) = c0;
    *reinterpret_cast<float4*>(&s_colw[wid][128 + lid * 4]) = c1;
    *reinterpret_cast<float4*>(&s_colw[wid][256 + lid * 4]) = c2;
    *reinterpret_cast<float4*>(&s_colw[wid][384 + lid * 4]) = c3;

    float sq0 = a0.x*a0.x + a0.y*a0.y + a0.z*a0.z + a0.w*a0.w
              + a1.x*a1.x + a1.y*a1.y + a1.z*a1.z + a1.w*a1.w
              + a2.x*a2.x + a2.y*a2.y + a2.z*a2.z + a2.w*a2.w
              + a3.x*a3.x + a3.y*a3.y + a3.z*a3.z + a3.w*a3.w;
    float sq1 = b0.x*b0.x + b0.y*b0.y + b0.z*b0.z + b0.w*b0.w
              + b1.x*b1.x + b1.y*b1.y + b1.z*b1.z + b1.w*b1.w
              + b2.x*b2.x + b2.y*b2.y + b2.z*b2.z + b2.w*b2.w
              + b3.x*b3.x + b3.y*b3.y + b3.z*b3.z + b3.w*b3.w;

    #pragma unroll
    for (int off = 16; off > 0; off >>= 1) {
        sq0 += __shfl_xor_sync(0xffffffffu, sq0, off);
        sq1 += __shfl_xor_sync(0xffffffffu, sq1, off);
    }
    // fire-and-forget RED: per-warp S and max (replicated)
    if (lid == 0) {
        const int rs = (blockIdx.x * WARPS_A + wid) & (SREP - 1);
        atomicAdd(&g_S_ll[rs],
                  (unsigned long long)__float2ll_rn((sq0 + sq1) * SCALE_F));
        atomicMax(&g_max_int[rs], __float_as_int(fmaxf(sq0, sq1)));
    }
    __syncthreads();

    // ---- combine 8 warps, push column REDs (fire-and-forget) ----
    const int rep = blockIdx.x & (NREP - 1);
    #pragma unroll
    for (int k = 0; k < 2; ++k) {
        const int c = tid + k * THREADS_A;
        float v = 0.f;
        #pragma unroll
        for (int w = 0; w < WARPS_A; ++w) v += s_colw[w][c];
        atomicAdd(&g_col_ll[rep][c],
                  (unsigned long long)__float2ll_rn(v * SCALE_F));
    }
}

__global__ void __launch_bounds__(512)
finalize_kernel(float* __restrict__ out) {
    __shared__ float s_w[16];
    __shared__ float s_sm[2];
    __shared__ float s_mx[2];

    const int tid = threadIdx.x;
    const int wid = tid >> 5;
    const int lid = tid & 31;

    // column totals: one column per thread (16 independent L2-hot loads)
    long long t = 0ll;
    #pragma unroll
    for (int r = 0; r < NREP; ++r)
        t += (long long)g_col_ll[r][tid];
    const float f = (float)t * INV_SCALE_F;
    float csq = f * f;

    #pragma unroll
    for (int off = 16; off > 0; off >>= 1)
        csq += __shfl_xor_sync(0xffffffffu, csq, off);
    if (lid == 0) s_w[wid] = csq;

    // S and max from replicated scalars (warps 0 and 1), all float
    if (tid < SREP) {
        float Sp = (float)(long long)g_S_ll[tid] * INV_SCALE_F;
        float Mp = __int_as_float(g_max_int[tid]);
        #pragma unroll
        for (int off = 16; off > 0; off >>= 1) {
            Sp += __shfl_xor_sync(0xffffffffu, Sp, off);
            Mp = fmaxf(Mp, __shfl_xor_sync(0xffffffffu, Mp, off));
        }
        if (lid == 0) { s_sm[wid] = Sp; s_mx[wid] = Mp; }
    }
    __syncthreads();

    // warp 0 combines the 16 per-warp ssq partials (log-depth)
    if (wid == 0) {
        float w = (lid < 16) ? s_w[lid] : 0.f;
        #pragma unroll
        for (int off = 8; off > 0; off >>= 1)
            w += __shfl_xor_sync(0xffffffffu, w, off);
        if (lid == 0) {
            const float ssq_total = w;
            const float S_total = s_sm[0] + s_sm[1];
            const float maxsq = fmaxf(s_mx[0], s_mx[1]);
            const float numer = 8192.0f * S_total - ssq_total;
            const float norm = sqrtf(maxsq);
            const float count = 0.5f * (float)N_ROWS * (float)(N_ROWS - 1);
            out[0] = numer / (norm * count);
        }
    }
    __syncthreads();   // all reads done -> safe to reset

    #pragma unroll
    for (int r = 0; r < NREP; ++r)
        g_col_ll[r][tid] = 0ull;
    if (tid < SREP) {
        g_S_ll[tid] = 0ull;
        g_max_int[tid] = 0;
    }
}

extern "C" void kernel_launch(void* const* d_in, const int* in_sizes, int n_in,
                              void* d_out, int out_size) {
    (void)in_sizes; (void)n_in; (void)out_size;
    const float* x = (const float*)d_in[0];
    float* out = (float*)d_out;
    stream_kernel<<<GRID_A, THREADS_A>>>(x);
    finalize_kernel<<<1, 512>>>(out);
}